// round 12
// baseline (speedup 1.0000x reference)
#include <cuda_runtime.h>
#include <cstdint>

// ImageRotator — cp.async(LDGSTS)-fed tiled gather.
// img: (32,1,512,512) fp32  angles: (8,) fp32 deg  out: (32,8,512,512) fp32
//
// TMA trapped on this stack (R8-R10); cp.async is the conservative way to get
// the fill out of the register-staged LDG+STS path. The 48x52 source window
// is 16B-aligned and clamped fully in-image, so every cp.async src is valid
// and per-texel clamping disappears. Gather uses per-tap clamped offsets
// (correct at image borders with a clamped window origin). One block =
// (angle, 16-image group, 32x32 output tile), double-buffered.

#define IMG_H 512
#define IMG_W 512
#define N_IMG 32
#define N_ANG 8
#define HW (IMG_H * IMG_W)
#define TILE 32
#define GRP 16
#define TW 52                 // window cols (floats): span<=48 +3 align slack; 208B = 16B mult
#define TH 48                 // window rows
#define NOPS ((TW / 4) * TH)  // 16B ops per window = 13*48 = 624

__device__ __forceinline__ void cp_async16(uint32_t smem_dst, const void* gsrc) {
    asm volatile("cp.async.ca.shared.global [%0], [%1], 16;"
                 :: "r"(smem_dst), "l"(gsrc) : "memory");
}
__device__ __forceinline__ void cp_commit() {
    asm volatile("cp.async.commit_group;" ::: "memory");
}
template <int N>
__device__ __forceinline__ void cp_wait() {
    asm volatile("cp.async.wait_group %0;" :: "n"(N) : "memory");
}

__global__ __launch_bounds__(256, 4) void rotate_cpasync(
    const float* __restrict__ img,
    const float* __restrict__ angles,
    float* __restrict__ out)
{
    __shared__ alignas(16) float sbuf[2][TH * TW];

    const int z   = blockIdx.z;            // 0..15
    const int a   = z >> 1;                // angle
    const int n0  = (z & 1) * GRP;         // first image of group
    const int tx0 = blockIdx.x * TILE;
    const int ty0 = blockIdx.y * TILE;
    const int tid = threadIdx.x;

    const float ang = angles[a] * 0.017453292519943295f;
    float sa, ca;
    sincosf(ang, &sa, &ca);                // sin FIRST
    const float cx = (IMG_W - 1) * 0.5f;
    const float cy = (IMG_H - 1) * 0.5f;

    // bbox via the SAME fmaf expression as per-pixel samples; -1 ULP margin.
    const float Xa = (float)tx0 - cx,  Xb = (float)(tx0 + TILE - 1) - cx;
    const float Ya = (float)ty0 - cy,  Yb = (float)(ty0 + TILE - 1) - cy;
    float sx0c = fmaf(ca, Xa, fmaf(-sa, Ya, cx));
    float sx1c = fmaf(ca, Xb, fmaf(-sa, Ya, cx));
    float sx2c = fmaf(ca, Xa, fmaf(-sa, Yb, cx));
    float sx3c = fmaf(ca, Xb, fmaf(-sa, Yb, cx));
    float sy0c = fmaf(sa, Xa, fmaf(ca, Ya, cy));
    float sy1c = fmaf(sa, Xb, fmaf(ca, Ya, cy));
    float sy2c = fmaf(sa, Xa, fmaf(ca, Yb, cy));
    float sy3c = fmaf(sa, Xb, fmaf(ca, Yb, cy));
    const int bx0 = (int)floorf(fminf(fminf(sx0c, sx1c), fminf(sx2c, sx3c))) - 1;
    const int by0 = (int)floorf(fminf(fminf(sy0c, sy1c), fminf(sy2c, sy3c))) - 1;

    // Window origin: x aligned down to 16B then clamped in-image; y clamped.
    // In-image part of the bbox is always covered (span<=48, +3 align <=51<=52).
    const int bxc = min(max(bx0 & ~3, 0), IMG_W - TW);
    const int byc = min(max(by0, 0), IMG_H - TH);

    // ---- n-invariant gather state: o00 + dx/dy + 4 weights per output ----
    const int orow = tid >> 3;             // 0..31
    const int ocol = (tid & 7) << 2;       // 0,4,...,28
    const int oy   = ty0 + orow;
    const float Yf = (float)oy - cy;

    int   o00[4], dxo[4], dyo[4];
    float wts[4][4];
#pragma unroll
    for (int j = 0; j < 4; j++) {
        int ox = tx0 + ocol + j;
        float Xf = (float)ox - cx;
        float sx = fmaf(ca, Xf, fmaf(-sa, Yf, cx));
        float sy = fmaf(sa, Xf, fmaf(ca, Yf, cy));
        float x0f = floorf(sx), y0f = floorf(sy);
        float wx = sx - x0f,   wy = sy - y0f;
        int x0 = (int)x0f, y0 = (int)y0f;
        bool vx0 = (x0 >= 0) & (x0 < IMG_W);
        bool vx1 = (x0 >= -1) & (x0 < IMG_W - 1);
        bool vy0 = (y0 >= 0) & (y0 < IMG_H);
        bool vy1 = (y0 >= -1) & (y0 < IMG_H - 1);
        float omwx = 1.0f - wx, omwy = 1.0f - wy;
        wts[j][0] = (vy0 && vx0) ? (omwy * omwx) : 0.0f;
        wts[j][1] = (vy0 && vx1) ? (omwy * wx)   : 0.0f;
        wts[j][2] = (vy1 && vx0) ? (wy * omwx)   : 0.0f;
        wts[j][3] = (vy1 && vx1) ? (wy * wx)     : 0.0f;
        // Per-tap clamped indices: nonzero-weight taps provably inside the
        // clamped window; weight-0 taps read a finite in-buffer texel.
        int xi0 = min(max(x0 - bxc,     0), TW - 1);
        int xi1 = min(max(x0 + 1 - bxc, 0), TW - 1);
        int yi0 = min(max(y0 - byc,     0), TH - 1);
        int yi1 = min(max(y0 + 1 - byc, 0), TH - 1);
        o00[j] = yi0 * TW + xi0;
        dxo[j] = xi1 - xi0;            // 0 or 1
        dyo[j] = (yi1 - yi0) * TW;     // 0 or TW
    }

    // ---- fill op addresses (n-invariant): each thread owns <=3 16B ops ----
    // op i (0..623): row r = i/13, col c = (i%13)*4 floats.
    const uint32_t sb0 = (uint32_t)__cvta_generic_to_shared(&sbuf[0][0]);
    const uint32_t sb1 = (uint32_t)__cvta_generic_to_shared(&sbuf[1][0]);
    const int winbase = byc * IMG_W + bxc;          // gmem float offset of window
    int gofs[3];   // gmem float offsets
    int sofs[3];   // smem byte offsets
    int nops = 0;
#pragma unroll
    for (int k = 0; k < 3; k++) {
        int i = tid + k * 256;
        if (i < NOPS) {
            int r = i / (TW / 4);
            int c = (i - r * (TW / 4)) * 4;
            gofs[nops] = winbase + r * IMG_W + c;
            sofs[nops] = (r * TW + c) * 4;
            nops++;
        }
    }

    // ---- prologue: async-fill buffers 0,1 with images n0, n0+1 ----
    {
        const float* ip = img + (size_t)n0 * HW;
        for (int q = 0; q < nops; q++) cp_async16(sb0 + sofs[q], ip + gofs[q]);
        cp_commit();
        ip += HW;
        for (int q = 0; q < nops; q++) cp_async16(sb1 + sofs[q], ip + gofs[q]);
        cp_commit();
    }

    float* op = out + ((size_t)n0 * N_ANG + a) * (size_t)HW
                    + (size_t)oy * IMG_W + (tx0 + ocol);

    for (int n = 0; n < GRP; n++) {
        const int s = n & 1;
        cp_wait<1>();          // oldest pending group (buffer s) complete
        __syncthreads();       // make all threads' fills visible

        const float* sb = sbuf[s];
        float acc[4];
#pragma unroll
        for (int j = 0; j < 4; j++) {
            int o = o00[j], dx = dxo[j], dy = dyo[j];
            float v00 = sb[o];
            float v01 = sb[o + dx];
            float v10 = sb[o + dy];
            float v11 = sb[o + dy + dx];
            acc[j] = fmaf(v00, wts[j][0],
                     fmaf(v01, wts[j][1],
                     fmaf(v10, wts[j][2], v11 * wts[j][3])));
        }
        *(float4*)op = make_float4(acc[0], acc[1], acc[2], acc[3]);
        op += (size_t)N_ANG * HW;

        __syncthreads();       // all reads of sbuf[s] done before refill
        if (n + 2 < GRP) {
            const float* ipn = img + (size_t)(n0 + n + 2) * HW;
            const uint32_t sbd = s ? sb1 : sb0;
            for (int q = 0; q < nops; q++) cp_async16(sbd + sofs[q], ipn + gofs[q]);
        }
        cp_commit();           // unconditional: keeps group count in lockstep
    }
}

extern "C" void kernel_launch(void* const* d_in, const int* in_sizes, int n_in,
                              void* d_out, int out_size) {
    const float* img;
    const float* angles;
    if (in_sizes[0] > in_sizes[1]) {
        img    = (const float*)d_in[0];
        angles = (const float*)d_in[1];
    } else {
        angles = (const float*)d_in[0];
        img    = (const float*)d_in[1];
    }
    float* out = (float*)d_out;

    dim3 grid(IMG_W / TILE, IMG_H / TILE, N_ANG * (N_IMG / GRP));  // (16,16,16)
    rotate_cpasync<<<grid, 256>>>(img, angles, out);
}

// round 14
// speedup vs baseline: 1.7037x; 1.7037x over previous
#include <cuda_runtime.h>
#include <cstdint>

// ImageRotator — tiled smem gather, affine fill, clamped window.
// img: (32,1,512,512) fp32  angles: (8,) fp32 deg  out: (32,8,512,512) fp32
//
// One block = (angle, 8-image group, 32x32 output tile), double-buffered.
// Window origin clamped in-image -> fill addresses are base+immediate
// (no per-texel clamping, no address arrays); gather uses per-tap clamped
// offsets (correctness proven in R12). Warp-per-row fill: coalesced LDG,
// conflict-free STS.

#define IMG_H 512
#define IMG_W 512
#define N_IMG 32
#define N_ANG 8
#define HW (IMG_H * IMG_W)
#define TILE 32
#define GRP 8
#define TW 48            // window cols: span <= 47 (31*(|c|+|s|)+2 taps+1 margin)
#define TH 48            // window rows
#define ST 49            // smem row stride: banks=(17r+c)%32 -> row & col conflict-free

__global__ __launch_bounds__(256, 5) void rotate_v6(
    const float* __restrict__ img,
    const float* __restrict__ angles,
    float* __restrict__ out)
{
    __shared__ float sbuf[2][TH * ST];

    const int z   = blockIdx.z;           // 0..31
    const int a   = z >> 2;               // angle
    const int n0  = (z & 3) * GRP;        // first image of group
    const int tx0 = blockIdx.x * TILE;
    const int ty0 = blockIdx.y * TILE;
    const int tid = threadIdx.x;

    const float ang = angles[a] * 0.017453292519943295f;
    float sa, ca;
    sincosf(ang, &sa, &ca);               // sin FIRST
    const float cx = (IMG_W - 1) * 0.5f;
    const float cy = (IMG_H - 1) * 0.5f;

    // bbox via the SAME fmaf expression as per-pixel samples; -1 ULP margin.
    const float Xa = (float)tx0 - cx,  Xb = (float)(tx0 + TILE - 1) - cx;
    const float Ya = (float)ty0 - cy,  Yb = (float)(ty0 + TILE - 1) - cy;
    float s0 = fmaf(ca, Xa, fmaf(-sa, Ya, cx));
    float s1 = fmaf(ca, Xb, fmaf(-sa, Ya, cx));
    float s2 = fmaf(ca, Xa, fmaf(-sa, Yb, cx));
    float s3 = fmaf(ca, Xb, fmaf(-sa, Yb, cx));
    float t0 = fmaf(sa, Xa, fmaf(ca, Ya, cy));
    float t1 = fmaf(sa, Xb, fmaf(ca, Ya, cy));
    float t2 = fmaf(sa, Xa, fmaf(ca, Yb, cy));
    float t3 = fmaf(sa, Xb, fmaf(ca, Yb, cy));
    const int bx0 = (int)floorf(fminf(fminf(s0, s1), fminf(s2, s3))) - 1;
    const int by0 = (int)floorf(fminf(fminf(t0, t1), fminf(t2, t3))) - 1;

    // Clamp window fully in-image: fill needs NO per-texel clamping; the
    // in-image part of the bbox (span <= 48) is always covered.
    const int bxc = min(max(bx0, 0), IMG_W - TW);
    const int byc = min(max(by0, 0), IMG_H - TH);

    // ---- n-invariant gather state (logic identical to R12, proven) ----
    const int orow = tid >> 3;            // 0..31
    const int ocol = (tid & 7) << 2;      // 0,4,...,28
    const int oy   = ty0 + orow;
    const float Yf = (float)oy - cy;

    int   o00[4];
    int   flags = 0;                      // 2 bits per output: dx, dy
    float wts[4][4];
#pragma unroll
    for (int j = 0; j < 4; j++) {
        int ox = tx0 + ocol + j;
        float Xf = (float)ox - cx;
        float sx = fmaf(ca, Xf, fmaf(-sa, Yf, cx));
        float sy = fmaf(sa, Xf, fmaf(ca, Yf, cy));
        float x0f = floorf(sx), y0f = floorf(sy);
        float wx = sx - x0f,   wy = sy - y0f;
        int x0 = (int)x0f, y0 = (int)y0f;
        bool vx0 = (x0 >= 0) & (x0 < IMG_W);
        bool vx1 = (x0 >= -1) & (x0 < IMG_W - 1);
        bool vy0 = (y0 >= 0) & (y0 < IMG_H);
        bool vy1 = (y0 >= -1) & (y0 < IMG_H - 1);
        float omwx = 1.0f - wx, omwy = 1.0f - wy;
        wts[j][0] = (vy0 && vx0) ? (omwy * omwx) : 0.0f;
        wts[j][1] = (vy0 && vx1) ? (omwy * wx)   : 0.0f;
        wts[j][2] = (vy1 && vx0) ? (wy * omwx)   : 0.0f;
        wts[j][3] = (vy1 && vx1) ? (wy * wx)     : 0.0f;
        // Per-tap clamped indices: nonzero-weight taps provably inside the
        // clamped window; weight-0 taps read a finite in-buffer texel.
        int xi0 = min(max(x0 - bxc,     0), TW - 1);
        int xi1 = min(max(x0 + 1 - bxc, 0), TW - 1);
        int yi0 = min(max(y0 - byc,     0), TH - 1);
        int yi1 = min(max(y0 + 1 - byc, 0), TH - 1);
        o00[j] = yi0 * ST + xi0;
        flags |= (xi1 - xi0) << (2 * j);          // dx bit
        flags |= (yi1 - yi0) << (2 * j + 1);      // dy bit
    }

    // ---- affine fill: warp = 32 contiguous floats of one row ----
    // rows r = (tid>>5) + 8*kr (kr 0..5), cols c = (tid&31) + kc (kc 0,16).
    // All addresses = base + compile-time constant. Cols 16..31 written twice
    // (same value) — benign, buys full coalescing with 256 threads on 48 cols.
    const int fr = tid >> 5;              // 0..7
    const int fc = tid & 31;              // 0..31
    const float* gbase0 = img + (size_t)n0 * HW + (byc + fr) * IMG_W + bxc + fc;
    float* sb_fill = &sbuf[0][fr * ST + fc];

#define FILL(dst, gsrc)                                                     \
    _Pragma("unroll")                                                       \
    for (int kr = 0; kr < 6; kr++) {                                        \
        _Pragma("unroll")                                                   \
        for (int kc = 0; kc < 2; kc++) {                                    \
            (dst)[(8 * kr) * ST + 16 * kc] =                                \
                __ldg((gsrc) + (8 * kr) * IMG_W + 16 * kc);                 \
        }                                                                   \
    }

    // prologue: buffer 0 <- image n0
    FILL(sb_fill, gbase0);
    __syncthreads();

    float* op = out + ((size_t)n0 * N_ANG + a) * (size_t)HW
                    + (size_t)oy * IMG_W + (tx0 + ocol);

    for (int n = 0; n < GRP; n++) {
        // prefetch image n0+n+1 into the other buffer
        if (n + 1 < GRP) {
            const float* g = gbase0 + (size_t)(n + 1) * HW;
            float* d = sb_fill + ((n + 1) & 1) * (TH * ST);
            FILL(d, g);
        }

        const float* sb = sbuf[n & 1];
        float acc[4];
#pragma unroll
        for (int j = 0; j < 4; j++) {
            int o  = o00[j];
            int dx = (flags >> (2 * j)) & 1;
            int dy = ((flags >> (2 * j + 1)) & 1) ? ST : 0;
            float v00 = sb[o];
            float v01 = sb[o + dx];
            float v10 = sb[o + dy];
            float v11 = sb[o + dy + dx];
            acc[j] = fmaf(v00, wts[j][0],
                     fmaf(v01, wts[j][1],
                     fmaf(v10, wts[j][2], v11 * wts[j][3])));
        }
        *(float4*)op = make_float4(acc[0], acc[1], acc[2], acc[3]);
        op += (size_t)N_ANG * HW;

        __syncthreads();   // prefetch visible; this buffer's reads done
    }
#undef FILL
}

extern "C" void kernel_launch(void* const* d_in, const int* in_sizes, int n_in,
                              void* d_out, int out_size) {
    const float* img;
    const float* angles;
    if (in_sizes[0] > in_sizes[1]) {
        img    = (const float*)d_in[0];
        angles = (const float*)d_in[1];
    } else {
        angles = (const float*)d_in[0];
        img    = (const float*)d_in[1];
    }
    float* out = (float*)d_out;

    dim3 grid(IMG_W / TILE, IMG_H / TILE, N_ANG * (N_IMG / GRP));  // (16,16,32)
    rotate_v6<<<grid, 256>>>(img, angles, out);
}